// round 15
// baseline (speedup 1.0000x reference)
#include <cuda_runtime.h>
#include <math.h>
#include <stdint.h>

// ---------------- constants ----------------
#define SHIFTn 4
#define LOGIT_MAX 4.6051702f

// mma_gemm: BM128 BN128 BK8, 6 stages. A stage 1536 fl (6144B), B stage 1088 fl (4352B)
#define G_STA_B 6144
#define G_STB_B 4352
#define G_SB_BASE 36864        // 6 * 6144
#define G_DSM 62976            // 6*(6144+4352)

// fused: BM64 BN256 BK8, 6 stages. A stage 768 fl (3072B), B stage 2112 fl (8448B)
#define F_STA_B 3072
#define F_STB_B 8448
#define F_SB_BASE 18432        // 6 * 3072
#define F_DSM 69120            // 6*(3072+8448); epilogue needs 67584 <= this

// ---------------- scratch ----------------
__device__ float g_q[33554432];
__device__ float g_k[33554432];
__device__ float g_v[33554432];
__device__ float g_attnout[33554432];  // windowed [t][C] (tf32-rounded)
__device__ float g_x1[33554432];       // natural [p][C]
__device__ float g_h[134217728];       // [t][1024] (tf32-rounded)
__device__ float g_tbl[225 * 8];
__device__ float g_bias[131072];       // [4 cls][8 h][64][64]
__device__ float g_wr[786432];         // tf32 weights

// ---------------- helpers ----------------
__device__ __forceinline__ float cvt_tf32f(float x) {
    unsigned r;
    asm("cvt.rna.tf32.f32 %0, %1;" : "=r"(r) : "f"(x));
    return __uint_as_float(r);
}
__device__ __forceinline__ unsigned cvt_tf32u(float x) {
    unsigned r;
    asm("cvt.rna.tf32.f32 %0, %1;" : "=r"(r) : "f"(x));
    return r;
}
__device__ __forceinline__ uint32_t smem_u32(const void* p) {
    uint32_t a;
    asm("{ .reg .u64 t; cvta.to.shared.u64 t, %1; cvt.u32.u64 %0, t; }" : "=r"(a) : "l"(p));
    return a;
}
__device__ __forceinline__ void cp16(uint32_t dst, const float* src) {
    asm volatile("cp.async.cg.shared.global [%0], [%1], 16;" :: "r"(dst), "l"(src));
}
#define CP_COMMIT() asm volatile("cp.async.commit_group;" ::: "memory")
#define CP_WAIT3() asm volatile("cp.async.wait_group 3;" ::: "memory")
#define CP_WAIT4() asm volatile("cp.async.wait_group 4;" ::: "memory")

__device__ __forceinline__ void mma_tf32(float* d, const unsigned* a, const unsigned* b) {
    asm volatile(
        "mma.sync.aligned.m16n8k8.row.col.f32.tf32.tf32.f32 "
        "{%0,%1,%2,%3},{%4,%5,%6,%7},{%8,%9},{%0,%1,%2,%3};"
        : "+f"(d[0]), "+f"(d[1]), "+f"(d[2]), "+f"(d[3])
        : "r"(a[0]), "r"(a[1]), "r"(a[2]), "r"(a[3]), "r"(b[0]), "r"(b[1]));
}

__device__ __forceinline__ size_t nat_pos(int t) {
    int w = t >> 6, n = t & 63;
    int b = w >> 6, wi = w & 63;
    int wh = wi >> 3, ww = wi & 7;
    int r = n >> 3, c = n & 7;
    int oh = (wh * 8 + r + SHIFTn) & 63;
    int ow = (ww * 8 + c + SHIFTn) & 63;
    return (size_t)(b * 4096 + oh * 64 + ow);
}

// ---------------- weight rounding ----------------
__global__ void round_w_kernel(const float* __restrict__ qkv, const float* __restrict__ proj,
                               const float* __restrict__ fc1, const float* __restrict__ fc2) {
    int i = blockIdx.x * 256 + threadIdx.x;
    int strd = gridDim.x * 256;
    for (int j = i; j < 196608; j += strd) g_wr[j] = cvt_tf32f(qkv[j]);
    for (int j = i; j < 65536; j += strd) g_wr[196608 + j] = cvt_tf32f(proj[j]);
    for (int j = i; j < 262144; j += strd) g_wr[262144 + j] = cvt_tf32f(fc1[j]);
    for (int j = i; j < 262144; j += strd) g_wr[524288 + j] = cvt_tf32f(fc2[j]);
}

// ---------------- CPB MLP table (16*sigmoid) ----------------
__global__ void cpb_kernel(const float* __restrict__ w1, const float* __restrict__ b1,
                           const float* __restrict__ w2) {
    int idx = blockIdx.x;
    int i = idx / 15, j = idx % 15;
    float a0 = (float)(i - 7) * (8.0f / 7.0f);
    float a1 = (float)(j - 7) * (8.0f / 7.0f);
    float r0 = copysignf(log2f(fabsf(a0) + 1.0f) * (1.0f / 3.0f), a0);
    float r1 = copysignf(log2f(fabsf(a1) + 1.0f) * (1.0f / 3.0f), a1);
    float acc[8];
#pragma unroll
    for (int h = 0; h < 8; h++) acc[h] = 0.0f;
    for (int jj = threadIdx.x; jj < 512; jj += 256) {
        float hv = fmaxf(fmaf(r0, w1[jj], fmaf(r1, w1[512 + jj], b1[jj])), 0.0f);
#pragma unroll
        for (int h = 0; h < 8; h++) acc[h] += hv * w2[jj * 8 + h];
    }
    __shared__ float red[256][8];
#pragma unroll
    for (int h = 0; h < 8; h++) red[threadIdx.x][h] = acc[h];
    __syncthreads();
    for (int s = 128; s > 0; s >>= 1) {
        if (threadIdx.x < s) {
#pragma unroll
            for (int h = 0; h < 8; h++) red[threadIdx.x][h] += red[threadIdx.x + s][h];
        }
        __syncthreads();
    }
    if (threadIdx.x < 8) {
        float v = red[0][threadIdx.x];
        g_tbl[idx * 8 + threadIdx.x] = 16.0f / (1.0f + expf(-v));
    }
}

// ---------------- bias+mask precompute ----------------
__global__ void bias_kernel() {
    int cls = blockIdx.x >> 3, h = blockIdx.x & 7;
    for (int idx = threadIdx.x; idx < 4096; idx += 256) {
        int ri = idx >> 6, cj = idx & 63;
        int rel = ((ri >> 3) - (cj >> 3) + 7) * 15 + ((ri & 7) - (cj & 7) + 7);
        float v = g_tbl[rel * 8 + h];
        int rr_i = (cls & 1) ? (((ri >> 3) < 4) ? 1 : 2) : 0;
        int rc_i = (cls & 2) ? (((ri & 7) < 4) ? 1 : 2) : 0;
        int rr_j = (cls & 1) ? (((cj >> 3) < 4) ? 1 : 2) : 0;
        int rc_j = (cls & 2) ? (((cj & 7) < 4) ? 1 : 2) : 0;
        if (rr_i * 3 + rc_i != rr_j * 3 + rc_j) v -= 100.0f;
        g_bias[blockIdx.x * 4096 + idx] = v;
    }
}

// ---------------- GEMM A: BM128 BN128 BK8, 6 stages, A-frag double buffer ---
// MODE 0: A=x (gather, consumer cvt), W=qkv -> q/k/v (+biases)
// MODE 2: A=g_x1 (consumer cvt),      W=fc1 -> gelu -> g_h (rounded)
template <int MODE>
__global__ void __launch_bounds__(256, 2)
mma_gemm(const float* __restrict__ Ain, const float* __restrict__ bias0,
         const float* __restrict__ bias1, int Ncols, int K) {
    extern __shared__ __align__(16) char dsm[];
    float* sA = (float*)dsm;
    float* sB = (float*)(dsm + G_SB_BASE);

    const float* A = (MODE == 0) ? Ain : g_x1;
    const float* W = (MODE == 0) ? g_wr : (g_wr + 262144);

    int tid = threadIdx.x;
    int lane = tid & 31, wid = tid >> 5;
    int wm = (wid & 3) * 32, wn = (wid >> 2) * 64;
    int t0 = blockIdx.y * 128, j0 = blockIdx.x * 128;

    int mA = tid >> 1, cA4 = (tid & 1) * 4;
    const float* aRow;
    {
        int t = t0 + mA;
        size_t rowb = (MODE == 0) ? nat_pos(t) * 256 : (size_t)t * (size_t)K;
        aRow = A + rowb + cA4;
    }
    uint32_t aDst = smem_u32(sA) + (uint32_t)(mA * 12 + cA4) * 4;
    const float* bSrc = W + (size_t)(tid >> 5) * Ncols + j0 + (tid & 31) * 4;
    uint32_t bDst = smem_u32(sB) + (uint32_t)((tid >> 5) * 136 + (tid & 31) * 4) * 4;

    float acc[2][8][4];
#pragma unroll
    for (int mt = 0; mt < 2; mt++)
#pragma unroll
        for (int nt = 0; nt < 8; nt++)
#pragma unroll
            for (int i = 0; i < 4; i++) acc[mt][nt][i] = 0.0f;

    int T = K >> 3;
    // prologue: fill 5 stages
#pragma unroll
    for (int s = 0; s < 5; s++) {
        cp16(aDst + (uint32_t)s * G_STA_B, aRow + s * 8);
        cp16(bDst + (uint32_t)s * G_STB_B, bSrc + (size_t)(s * 8) * Ncols);
        CP_COMMIT();
    }
    CP_WAIT3();          // stages 0,1 complete (5 committed, <=3 pending)
    __syncthreads();

    int r = lane & 3, q = lane >> 2;
    unsigned af[2][2][4];  // [buf][mt]
    int cur = 0;
    {
        const float* Ap = sA;
#pragma unroll
        for (int mt = 0; mt < 2; mt++) {
            int mb = (wm + mt * 16 + q) * 12;
            af[0][mt][0] = cvt_tf32u(Ap[mb + r]);
            af[0][mt][1] = cvt_tf32u(Ap[mb + 96 + r]);
            af[0][mt][2] = cvt_tf32u(Ap[mb + 4 + r]);
            af[0][mt][3] = cvt_tf32u(Ap[mb + 96 + 4 + r]);
        }
    }

    for (int kt = 0; kt < T; kt++) {
        int kn = kt + 5;
        if (kn < T) {
            int st = kn % 6;
            cp16(aDst + (uint32_t)st * G_STA_B, aRow + kn * 8);
            cp16(bDst + (uint32_t)st * G_STB_B, bSrc + (size_t)(kn * 8) * Ncols);
        }
        CP_COMMIT();
        CP_WAIT4();

        int nxt = cur ^ 1;
        if (kt + 1 < T) {
            const float* Ap = sA + ((kt + 1) % 6) * 1536;
#pragma unroll
            for (int mt = 0; mt < 2; mt++) {
                int mb = (wm + mt * 16 + q) * 12;
                af[nxt][mt][0] = cvt_tf32u(Ap[mb + r]);
                af[nxt][mt][1] = cvt_tf32u(Ap[mb + 96 + r]);
                af[nxt][mt][2] = cvt_tf32u(Ap[mb + 4 + r]);
                af[nxt][mt][3] = cvt_tf32u(Ap[mb + 96 + 4 + r]);
            }
        }

        const float* Bp = sB + (kt % 6) * 1088;
#pragma unroll
        for (int nt = 0; nt < 8; nt++) {
            int cn = wn + nt * 8 + q;
            unsigned bf[2] = {__float_as_uint(Bp[r * 136 + cn]),
                              __float_as_uint(Bp[(r + 4) * 136 + cn])};
            mma_tf32(acc[0][nt], af[cur][0], bf);
            mma_tf32(acc[1][nt], af[cur][1], bf);
        }
        __syncthreads();
        cur = nxt;
    }

    // epilogue
#pragma unroll
    for (int mt = 0; mt < 2; mt++) {
#pragma unroll
        for (int i2 = 0; i2 < 2; i2++) {
            int row = wm + mt * 16 + (lane >> 2) + 8 * i2;
            int t = t0 + row;
            int w = t >> 6, n = t & 63;
#pragma unroll
            for (int nt = 0; nt < 8; nt++) {
#pragma unroll
                for (int j = 0; j < 2; j++) {
                    int col = j0 + wn + nt * 8 + (lane & 3) * 2 + j;
                    float v = acc[mt][nt][i2 * 2 + j];
                    if (MODE == 0) {
                        int part = col >> 8;
                        int hh = (col >> 5) & 7;
                        int hd = col & 31;
                        if (part == 0) v += bias0[col];
                        else if (part == 2) v += bias1[col - 512];
                        size_t dst = ((size_t)(w * 8 + hh) * 64 + n) * 32 + hd;
                        if (part == 0) g_q[dst] = v;
                        else if (part == 1) g_k[dst] = v;
                        else g_v[dst] = v;
                    } else {
                        v += bias0[col];
                        v = 0.5f * v * (1.0f + erff(v * 0.70710678118654752f));
                        g_h[(size_t)t * 1024 + col] = cvt_tf32f(v);
                    }
                }
            }
        }
    }
}

// ---------------- GEMM B (fused LN): BM64 BN256 BK8, 6 stages ---------------
// MODE 1: A=g_attnout, W=proj -> +proj_b, LN, +x -> g_x1 (natural)
// MODE 3: A=g_h,       W=fc2  -> +fc2_b, LN, +g_x1 -> out
template <int MODE>
__global__ void __launch_bounds__(256, 2)
mma_gemm_fused(const float* __restrict__ bias0, const float* __restrict__ gamma,
               const float* __restrict__ beta, const float* __restrict__ basep,
               float* __restrict__ outp, int K) {
    extern __shared__ __align__(16) char dsm[];
    float* sA = (float*)dsm;
    float* sB = (float*)(dsm + F_SB_BASE);

    const float* A = (MODE == 1) ? g_attnout : g_h;
    const float* W = (MODE == 1) ? (g_wr + 196608) : (g_wr + 524288);

    int tid = threadIdx.x;
    int lane = tid & 31, wid = tid >> 5;
    int wm = (wid & 1) * 32, wn = (wid >> 1) * 64;
    int t0 = blockIdx.x * 64;

    int mA = tid >> 1, cA4 = (tid & 1) * 4;
    const float* aRow = A + (size_t)(t0 + mA) * (size_t)K + cA4;
    uint32_t aDst = smem_u32(sA) + (uint32_t)(mA * 12 + cA4) * 4;
    bool doA = (tid < 128);

    int kB = tid >> 5, n8 = (tid & 31) * 8;
    const float* bSrc = W + (size_t)kB * 256 + n8;
    uint32_t bDst = smem_u32(sB) + (uint32_t)(kB * 264 + n8) * 4;

    float acc[2][8][4];
#pragma unroll
    for (int mt = 0; mt < 2; mt++)
#pragma unroll
        for (int nt = 0; nt < 8; nt++)
#pragma unroll
            for (int i = 0; i < 4; i++) acc[mt][nt][i] = 0.0f;

    int T = K >> 3;
#pragma unroll
    for (int s = 0; s < 5; s++) {
        if (doA) cp16(aDst + (uint32_t)s * F_STA_B, aRow + s * 8);
        cp16(bDst + (uint32_t)s * F_STB_B, bSrc + (size_t)(s * 8) * 256);
        cp16(bDst + 16 + (uint32_t)s * F_STB_B, bSrc + 4 + (size_t)(s * 8) * 256);
        CP_COMMIT();
    }
    CP_WAIT3();
    __syncthreads();

    int r = lane & 3, q = lane >> 2;
    unsigned af[2][2][4];
    int cur = 0;
    {
        const float* Ap = sA;
#pragma unroll
        for (int mt = 0; mt < 2; mt++) {
            int mb = (wm + mt * 16 + q) * 12;
            af[0][mt][0] = __float_as_uint(Ap[mb + r]);
            af[0][mt][1] = __float_as_uint(Ap[mb + 96 + r]);
            af[0][mt][2] = __float_as_uint(Ap[mb + 4 + r]);
            af[0][mt][3] = __float_as_uint(Ap[mb + 96 + 4 + r]);
        }
    }

    for (int kt = 0; kt < T; kt++) {
        int kn = kt + 5;
        if (kn < T) {
            int st = kn % 6;
            if (doA) cp16(aDst + (uint32_t)st * F_STA_B, aRow + kn * 8);
            cp16(bDst + (uint32_t)st * F_STB_B, bSrc + (size_t)(kn * 8) * 256);
            cp16(bDst + 16 + (uint32_t)st * F_STB_B, bSrc + 4 + (size_t)(kn * 8) * 256);
        }
        CP_COMMIT();
        CP_WAIT4();

        int nxt = cur ^ 1;
        if (kt + 1 < T) {
            const float* Ap = sA + ((kt + 1) % 6) * 768;
#pragma unroll
            for (int mt = 0; mt < 2; mt++) {
                int mb = (wm + mt * 16 + q) * 12;
                af[nxt][mt][0] = __float_as_uint(Ap[mb + r]);
                af[nxt][mt][1] = __float_as_uint(Ap[mb + 96 + r]);
                af[nxt][mt][2] = __float_as_uint(Ap[mb + 4 + r]);
                af[nxt][mt][3] = __float_as_uint(Ap[mb + 96 + 4 + r]);
            }
        }

        const float* Bp = sB + (kt % 6) * 2112;
#pragma unroll
        for (int nt = 0; nt < 8; nt++) {
            int cn = wn + nt * 8 + q;
            unsigned bf[2] = {__float_as_uint(Bp[r * 264 + cn]),
                              __float_as_uint(Bp[(r + 4) * 264 + cn])};
            mma_tf32(acc[0][nt], af[cur][0], bf);
            mma_tf32(acc[1][nt], af[cur][1], bf);
        }
        __syncthreads();
        cur = nxt;
    }

    // ---- fused epilogue: stage C, per-row LN + residual ----
    __syncthreads();
    float* Cs = (float*)dsm;  // [64][264]
#pragma unroll
    for (int mt = 0; mt < 2; mt++) {
#pragma unroll
        for (int i2 = 0; i2 < 2; i2++) {
            int row = wm + mt * 16 + (lane >> 2) + 8 * i2;
#pragma unroll
            for (int nt = 0; nt < 8; nt++) {
#pragma unroll
                for (int j = 0; j < 2; j++) {
                    int col = wn + nt * 8 + (lane & 3) * 2 + j;
                    Cs[row * 264 + col] = acc[mt][nt][i2 * 2 + j];
                }
            }
        }
    }
    __syncthreads();

    int c8 = lane * 8;
    float4 bv0 = *(const float4*)&bias0[c8];
    float4 bv1 = *(const float4*)&bias0[c8 + 4];
    float4 gv0 = *(const float4*)&gamma[c8];
    float4 gv1 = *(const float4*)&gamma[c8 + 4];
    float4 be0 = *(const float4*)&beta[c8];
    float4 be1 = *(const float4*)&beta[c8 + 4];

    for (int rr = 0; rr < 8; rr++) {
        int row = wid * 8 + rr;
        float4 a = *(const float4*)&Cs[row * 264 + c8];
        float4 c = *(const float4*)&Cs[row * 264 + c8 + 4];
        a.x += bv0.x; a.y += bv0.y; a.z += bv0.z; a.w += bv0.w;
        c.x += bv1.x; c.y += bv1.y; c.z += bv1.z; c.w += bv1.w;
        float s = a.x + a.y + a.z + a.w + c.x + c.y + c.z + c.w;
        float s2 = a.x * a.x + a.y * a.y + a.z * a.z + a.w * a.w +
                   c.x * c.x + c.y * c.y + c.z * c.z + c.w * c.w;
#pragma unroll
        for (int o = 16; o > 0; o >>= 1) {
            s += __shfl_xor_sync(0xffffffffu, s, o);
            s2 += __shfl_xor_sync(0xffffffffu, s2, o);
        }
        float mu = s * (1.0f / 256.0f);
        float var = s2 * (1.0f / 256.0f) - mu * mu;
        float inv = rsqrtf(var + 1e-5f);

        int t = t0 + row;
        size_t p = (MODE == 1) ? nat_pos(t) : (size_t)t;
        size_t off = p * 256 + c8;
        const float* base = (MODE == 1) ? basep : g_x1;
        float* dst = (MODE == 1) ? g_x1 : outp;
        float4 ba = *(const float4*)&base[off];
        float4 bc = *(const float4*)&base[off + 4];
        float4 r0, r1;
        r0.x = ba.x + (a.x - mu) * inv * gv0.x + be0.x;
        r0.y = ba.y + (a.y - mu) * inv * gv0.y + be0.y;
        r0.z = ba.z + (a.z - mu) * inv * gv0.z + be0.z;
        r0.w = ba.w + (a.w - mu) * inv * gv0.w + be0.w;
        r1.x = bc.x + (c.x - mu) * inv * gv1.x + be1.x;
        r1.y = bc.y + (c.y - mu) * inv * gv1.y + be1.y;
        r1.z = bc.z + (c.z - mu) * inv * gv1.z + be1.z;
        r1.w = bc.w + (c.w - mu) * inv * gv1.w + be1.w;
        *(float4*)&dst[off] = r0;
        *(float4*)&dst[off + 4] = r1;
    }
}

// ---------------- windowed cosine attention ----------------
__global__ void attn_kernel(const float* __restrict__ logit_scale) {
    __shared__ __align__(16) float qT[32][68];
    __shared__ __align__(16) float kT[32][68];
    __shared__ __align__(16) float vS[64][32];
    __shared__ __align__(16) float S[64][68];
    __shared__ float qn[64], kn[64];

    int w = blockIdx.x, h = blockIdx.y;
    int tid = threadIdx.x;
    size_t base = (size_t)(w * 8 + h) * 2048;

    for (int idx = tid; idx < 2048; idx += 256) {
        int n = idx >> 5, d = idx & 31;
        qT[d][n] = g_q[base + idx];
        kT[d][n] = g_k[base + idx];
        vS[n][d] = g_v[base + idx];
    }
    __syncthreads();

    float sc = __expf(fminf(logit_scale[h], LOGIT_MAX));
    if (tid < 64) {
        float s = 0.0f;
#pragma unroll
        for (int d = 0; d < 32; d++) s = fmaf(qT[d][tid], qT[d][tid], s);
        qn[tid] = rsqrtf(fmaxf(s, 1e-12f)) * sc;
    } else if (tid < 128) {
        int n = tid - 64;
        float s = 0.0f;
#pragma unroll
        for (int d = 0; d < 32; d++) s = fmaf(kT[d][n], kT[d][n], s);
        kn[n] = rsqrtf(fmaxf(s, 1e-12f));
    }
    __syncthreads();

    for (int idx = tid; idx < 2048; idx += 256) {
        int d = idx >> 6, n = idx & 63;
        qT[d][n] *= qn[n];
        kT[d][n] *= kn[n];
    }
    __syncthreads();

    int ty = tid >> 4, tx = tid & 15;
    float acc[4][4];
#pragma unroll
    for (int i = 0; i < 4; i++)
#pragma unroll
        for (int j = 0; j < 4; j++) acc[i][j] = 0.0f;

#pragma unroll
    for (int kk = 0; kk < 32; kk++) {
        float4 avv = *(const float4*)&qT[kk][ty * 4];
        float4 bvv = *(const float4*)&kT[kk][tx * 4];
        float a4[4] = {avv.x, avv.y, avv.z, avv.w};
        float b4[4] = {bvv.x, bvv.y, bvv.z, bvv.w};
#pragma unroll
        for (int i = 0; i < 4; i++)
#pragma unroll
            for (int j = 0; j < 4; j++) acc[i][j] = fmaf(a4[i], b4[j], acc[i][j]);
    }

    int wi = w & 63;
    int cls = (((wi >> 3) == 7) ? 1 : 0) | (((wi & 7) == 7) ? 2 : 0);
    const float* Bp = g_bias + ((size_t)(cls * 8 + h) << 12);
#pragma unroll
    for (int i = 0; i < 4; i++) {
        int ri = ty * 4 + i;
        float4 bv = *(const float4*)&Bp[ri * 64 + tx * 4];
        float v4[4];
        v4[0] = acc[i][0] + bv.x;
        v4[1] = acc[i][1] + bv.y;
        v4[2] = acc[i][2] + bv.z;
        v4[3] = acc[i][3] + bv.w;
        float m = fmaxf(fmaxf(v4[0], v4[1]), fmaxf(v4[2], v4[3]));
#pragma unroll
        for (int o = 8; o > 0; o >>= 1) m = fmaxf(m, __shfl_xor_sync(0xffffffffu, m, o));
        float s = 0.0f;
#pragma unroll
        for (int j = 0; j < 4; j++) {
            v4[j] = __expf(v4[j] - m);
            s += v4[j];
        }
#pragma unroll
        for (int o = 8; o > 0; o >>= 1) s += __shfl_xor_sync(0xffffffffu, s, o);
        float inv = 1.0f / s;
        float4 sv = make_float4(v4[0] * inv, v4[1] * inv, v4[2] * inv, v4[3] * inv);
        *(float4*)&S[ri][tx * 4] = sv;
    }
    __syncthreads();

    int ty2 = tid >> 3, tx2 = tid & 7;
    float o0[4] = {0, 0, 0, 0}, o1[4] = {0, 0, 0, 0};
#pragma unroll
    for (int mb = 0; mb < 16; mb++) {
        float4 s0 = *(const float4*)&S[ty2][mb * 4];
        float4 s1 = *(const float4*)&S[ty2 + 32][mb * 4];
        float p0[4] = {s0.x, s0.y, s0.z, s0.w};
        float p1[4] = {s1.x, s1.y, s1.z, s1.w};
#pragma unroll
        for (int e = 0; e < 4; e++) {
            float4 vv = *(const float4*)&vS[mb * 4 + e][tx2 * 4];
            float v4[4] = {vv.x, vv.y, vv.z, vv.w};
#pragma unroll
            for (int j = 0; j < 4; j++) {
                o0[j] = fmaf(p0[e], v4[j], o0[j]);
                o1[j] = fmaf(p1[e], v4[j], o1[j]);
            }
        }
    }
    {
        size_t d0 = (size_t)(w * 64 + ty2) * 256 + h * 32 + tx2 * 4;
        size_t d1 = (size_t)(w * 64 + ty2 + 32) * 256 + h * 32 + tx2 * 4;
        *(float4*)&g_attnout[d0] = make_float4(cvt_tf32f(o0[0]), cvt_tf32f(o0[1]),
                                               cvt_tf32f(o0[2]), cvt_tf32f(o0[3]));
        *(float4*)&g_attnout[d1] = make_float4(cvt_tf32f(o1[0]), cvt_tf32f(o1[1]),
                                               cvt_tf32f(o1[2]), cvt_tf32f(o1[3]));
    }
}

// ---------------- launch ----------------
extern "C" void kernel_launch(void* const* d_in, const int* in_sizes, int n_in,
                              void* d_out, int out_size) {
    const float* x = (const float*)d_in[0];
    const float* qkv_w = (const float*)d_in[1];
    const float* q_bias = (const float*)d_in[2];
    const float* v_bias = (const float*)d_in[3];
    const float* logit_scale = (const float*)d_in[4];
    const float* cpb_w1 = (const float*)d_in[5];
    const float* cpb_b1 = (const float*)d_in[6];
    const float* cpb_w2 = (const float*)d_in[7];
    const float* proj_w = (const float*)d_in[8];
    const float* proj_b = (const float*)d_in[9];
    const float* norm1_g = (const float*)d_in[10];
    const float* norm1_b = (const float*)d_in[11];
    const float* fc1_w = (const float*)d_in[12];
    const float* fc1_b = (const float*)d_in[13];
    const float* fc2_w = (const float*)d_in[14];
    const float* fc2_b = (const float*)d_in[15];
    const float* norm2_g = (const float*)d_in[16];
    const float* norm2_b = (const float*)d_in[17];
    float* out = (float*)d_out;

    static int smem_set = 0;
    if (!smem_set) {
        cudaFuncSetAttribute(mma_gemm<0>, cudaFuncAttributeMaxDynamicSharedMemorySize, G_DSM);
        cudaFuncSetAttribute(mma_gemm<2>, cudaFuncAttributeMaxDynamicSharedMemorySize, G_DSM);
        cudaFuncSetAttribute(mma_gemm_fused<1>, cudaFuncAttributeMaxDynamicSharedMemorySize, F_DSM);
        cudaFuncSetAttribute(mma_gemm_fused<3>, cudaFuncAttributeMaxDynamicSharedMemorySize, F_DSM);
        smem_set = 1;
    }

    round_w_kernel<<<512, 256>>>(qkv_w, proj_w, fc1_w, fc2_w);
    cpb_kernel<<<225, 256>>>(cpb_w1, cpb_b1, cpb_w2);
    bias_kernel<<<32, 256>>>();

    mma_gemm<0><<<dim3(6, 1024), 256, G_DSM>>>(x, q_bias, v_bias, 768, 256);
    attn_kernel<<<dim3(2048, 8), 256>>>(logit_scale);
    mma_gemm_fused<1><<<2048, 256, F_DSM>>>(proj_b, norm1_g, norm1_b, x, nullptr, 256);
    mma_gemm<2><<<dim3(8, 1024), 256, G_DSM>>>(nullptr, fc1_b, nullptr, 1024, 256);
    mma_gemm_fused<3><<<2048, 256, F_DSM>>>(fc2_b, norm2_g, norm2_b, nullptr, out, 1024);

    (void)in_sizes; (void)n_in; (void)out_size;
}

// round 16
// speedup vs baseline: 1.6017x; 1.6017x over previous
#include <cuda_runtime.h>
#include <cuda_fp16.h>
#include <math.h>
#include <stdint.h>

// ---------------- constants ----------------
#define SHIFTn 4
#define LOGIT_MAX 4.6051702f

// gemm: BM128 BN128 BK16, 4 stages. A stage 128x24 halfs = 6144B, B same.
#define G_ST_B 6144
#define G_SB_BASE 24576
#define G_DSM 49152
// fused: BM64 BN256 BK16, 4 stages. A 64x24 = 3072B, B 256x24 = 12288B.
#define F_STA_B 3072
#define F_STB_B 12288
#define F_SB_BASE 12288
#define F_DSM 67584            // epilogue stage [64][264] floats

// ---------------- scratch ----------------
__device__ float  g_q[33554432];
__device__ float  g_k[33554432];
__device__ float  g_v[33554432];
__device__ __half g_xh[33554432];       // x in fp16 (natural layout)
__device__ __half g_attnout[33554432];  // windowed [t][C] fp16
__device__ float  g_x1[33554432];       // natural [p][C] fp32 (residual base)
__device__ __half g_x1h[33554432];      // natural [p][C] fp16 (fc1 input)
__device__ __half g_hh[134217728];      // [t][1024] fp16 (fc2 input)
__device__ float  g_tbl[225 * 8];
__device__ float  g_bias[131072];       // [4 cls][8 h][64][64]
__device__ __half g_whT[786432];        // W^T fp16: qkv@0 [768][256], proj@196608 [256][256],
                                        // fc1@262144 [1024][256], fc2@524288 [256][1024]

// ---------------- helpers ----------------
__device__ __forceinline__ uint32_t smem_u32(const void* p) {
    uint32_t a;
    asm("{ .reg .u64 t; cvta.to.shared.u64 t, %1; cvt.u32.u64 %0, t; }" : "=r"(a) : "l"(p));
    return a;
}
__device__ __forceinline__ void cp16(uint32_t dst, const void* src) {
    asm volatile("cp.async.cg.shared.global [%0], [%1], 16;" :: "r"(dst), "l"(src));
}
#define CP_COMMIT() asm volatile("cp.async.commit_group;" ::: "memory")
#define CP_WAIT2() asm volatile("cp.async.wait_group 2;" ::: "memory")

__device__ __forceinline__ void mma_f16(float* d, const unsigned* a, const unsigned* b) {
    asm volatile(
        "mma.sync.aligned.m16n8k16.row.col.f32.f16.f16.f32 "
        "{%0,%1,%2,%3},{%4,%5,%6,%7},{%8,%9},{%0,%1,%2,%3};"
        : "+f"(d[0]), "+f"(d[1]), "+f"(d[2]), "+f"(d[3])
        : "r"(a[0]), "r"(a[1]), "r"(a[2]), "r"(a[3]), "r"(b[0]), "r"(b[1]));
}

__device__ __forceinline__ size_t nat_pos(int t) {
    int w = t >> 6, n = t & 63;
    int b = w >> 6, wi = w & 63;
    int wh = wi >> 3, ww = wi & 7;
    int r = n >> 3, c = n & 7;
    int oh = (wh * 8 + r + SHIFTn) & 63;
    int ow = (ww * 8 + c + SHIFTn) & 63;
    return (size_t)(b * 4096 + oh * 64 + ow);
}

// ---------------- prework ----------------
__global__ void half_w_kernel(const float* __restrict__ qkv, const float* __restrict__ proj,
                              const float* __restrict__ fc1, const float* __restrict__ fc2) {
    int i = blockIdx.x * 256 + threadIdx.x;
    int strd = gridDim.x * 256;
    for (int j = i; j < 196608; j += strd) {
        int n = j >> 8, k = j & 255;
        g_whT[j] = __float2half_rn(qkv[k * 768 + n]);
    }
    for (int j = i; j < 65536; j += strd) {
        int n = j >> 8, k = j & 255;
        g_whT[196608 + j] = __float2half_rn(proj[k * 256 + n]);
    }
    for (int j = i; j < 262144; j += strd) {
        int n = j >> 8, k = j & 255;
        g_whT[262144 + j] = __float2half_rn(fc1[k * 1024 + n]);
    }
    for (int j = i; j < 262144; j += strd) {
        int n = j >> 10, k = j & 1023;
        g_whT[524288 + j] = __float2half_rn(fc2[k * 256 + n]);
    }
}

__global__ void x_half_kernel(const float* __restrict__ x) {
    size_t i = (size_t)(blockIdx.x * 256 + threadIdx.x) * 4;
    size_t strd = (size_t)gridDim.x * 1024;
    for (; i < 33554432ull; i += strd) {
        float4 v = *(const float4*)&x[i];
        __half2 a = __floats2half2_rn(v.x, v.y);
        __half2 b = __floats2half2_rn(v.z, v.w);
        *(uint2*)&g_xh[i] = make_uint2(*(unsigned*)&a, *(unsigned*)&b);
    }
}

// ---------------- CPB MLP table (16*sigmoid) ----------------
__global__ void cpb_kernel(const float* __restrict__ w1, const float* __restrict__ b1,
                           const float* __restrict__ w2) {
    int idx = blockIdx.x;
    int i = idx / 15, j = idx % 15;
    float a0 = (float)(i - 7) * (8.0f / 7.0f);
    float a1 = (float)(j - 7) * (8.0f / 7.0f);
    float r0 = copysignf(log2f(fabsf(a0) + 1.0f) * (1.0f / 3.0f), a0);
    float r1 = copysignf(log2f(fabsf(a1) + 1.0f) * (1.0f / 3.0f), a1);
    float acc[8];
#pragma unroll
    for (int h = 0; h < 8; h++) acc[h] = 0.0f;
    for (int jj = threadIdx.x; jj < 512; jj += 256) {
        float hv = fmaxf(fmaf(r0, w1[jj], fmaf(r1, w1[512 + jj], b1[jj])), 0.0f);
#pragma unroll
        for (int h = 0; h < 8; h++) acc[h] += hv * w2[jj * 8 + h];
    }
    __shared__ float red[256][8];
#pragma unroll
    for (int h = 0; h < 8; h++) red[threadIdx.x][h] = acc[h];
    __syncthreads();
    for (int s = 128; s > 0; s >>= 1) {
        if (threadIdx.x < s) {
#pragma unroll
            for (int h = 0; h < 8; h++) red[threadIdx.x][h] += red[threadIdx.x + s][h];
        }
        __syncthreads();
    }
    if (threadIdx.x < 8) {
        float v = red[0][threadIdx.x];
        g_tbl[idx * 8 + threadIdx.x] = 16.0f / (1.0f + expf(-v));
    }
}

// ---------------- bias+mask precompute ----------------
__global__ void bias_kernel() {
    int cls = blockIdx.x >> 3, h = blockIdx.x & 7;
    for (int idx = threadIdx.x; idx < 4096; idx += 256) {
        int ri = idx >> 6, cj = idx & 63;
        int rel = ((ri >> 3) - (cj >> 3) + 7) * 15 + ((ri & 7) - (cj & 7) + 7);
        float v = g_tbl[rel * 8 + h];
        int rr_i = (cls & 1) ? (((ri >> 3) < 4) ? 1 : 2) : 0;
        int rc_i = (cls & 2) ? (((ri & 7) < 4) ? 1 : 2) : 0;
        int rr_j = (cls & 1) ? (((cj >> 3) < 4) ? 1 : 2) : 0;
        int rc_j = (cls & 2) ? (((cj & 7) < 4) ? 1 : 2) : 0;
        if (rr_i * 3 + rc_i != rr_j * 3 + rc_j) v -= 100.0f;
        g_bias[blockIdx.x * 4096 + idx] = v;
    }
}

// ---------------- fp16 GEMM A: BM128 BN128 BK16, 4 stages ------------------
// MODE 0: A=g_xh (gather), W=qkv^T -> q/k/v (+biases, fp32 out)
// MODE 2: A=g_x1h,         W=fc1^T -> gelu -> g_hh (fp16 out)
template <int MODE>
__global__ void __launch_bounds__(256, 2)
mma_gemm(const float* __restrict__ bias0, const float* __restrict__ bias1,
         int Ncols, int K) {
    extern __shared__ __align__(16) char dsm[];
    __half* sA = (__half*)dsm;                   // 4 stages x 3072 halfs (row stride 24)
    __half* sB = (__half*)(dsm + G_SB_BASE);     // 4 stages x 3072 halfs

    const __half* A = (MODE == 0) ? g_xh : g_x1h;
    const __half* W = (MODE == 0) ? g_whT : (g_whT + 262144);

    int tid = threadIdx.x;
    int lane = tid & 31, wid = tid >> 5;
    int wm = (wid & 3) * 32, wn = (wid >> 2) * 64;
    int t0 = blockIdx.y * 128, j0 = blockIdx.x * 128;

    // A producer: row = tid>>1 (128 rows), chunk = tid&1 (8 halfs = 16B)
    int rowA = tid >> 1, chA = tid & 1;
    const __half* aSrc;
    {
        int t = t0 + rowA;
        size_t rowb = (MODE == 0) ? nat_pos(t) * 256 : (size_t)t * (size_t)K;
        aSrc = A + rowb + chA * 8;
    }
    uint32_t aDst = smem_u32(sA) + (uint32_t)(rowA * 48 + chA * 16);
    // B producer: n-row = tid>>1, chunk = tid&1
    const __half* bSrc = W + (size_t)(j0 + (tid >> 1)) * K + (tid & 1) * 8;
    uint32_t bDst = smem_u32(sB) + (uint32_t)((tid >> 1) * 48 + (tid & 1) * 16);

    float acc[2][8][4];
#pragma unroll
    for (int mt = 0; mt < 2; mt++)
#pragma unroll
        for (int nt = 0; nt < 8; nt++)
#pragma unroll
            for (int i = 0; i < 4; i++) acc[mt][nt][i] = 0.0f;

    int T = K >> 4;
#pragma unroll
    for (int s = 0; s < 3; s++) {
        cp16(aDst + (uint32_t)s * G_ST_B, aSrc + s * 16);
        cp16(bDst + (uint32_t)s * G_ST_B, bSrc + s * 16);
        CP_COMMIT();
    }

    int r = lane & 3, q = lane >> 2;
    for (int kt = 0; kt < T; kt++) {
        CP_WAIT2();
        __syncthreads();
        int kn = kt + 3;
        if (kn < T) {
            int st = kn & 3;
            cp16(aDst + (uint32_t)st * G_ST_B, aSrc + kn * 16);
            cp16(bDst + (uint32_t)st * G_ST_B, bSrc + kn * 16);
        }
        CP_COMMIT();

        const __half* Ap = sA + (kt & 3) * 3072;
        const __half* Bp = sB + (kt & 3) * 3072;
        unsigned af[2][4];
#pragma unroll
        for (int mt = 0; mt < 2; mt++) {
            int m0 = (wm + mt * 16 + q) * 24;
            af[mt][0] = *(const unsigned*)&Ap[m0 + 2 * r];
            af[mt][1] = *(const unsigned*)&Ap[m0 + 192 + 2 * r];      // row +8
            af[mt][2] = *(const unsigned*)&Ap[m0 + 2 * r + 8];
            af[mt][3] = *(const unsigned*)&Ap[m0 + 192 + 2 * r + 8];
        }
#pragma unroll
        for (int nt = 0; nt < 8; nt++) {
            int n0 = (wn + nt * 8 + q) * 24;
            unsigned bf[2] = {*(const unsigned*)&Bp[n0 + 2 * r],
                              *(const unsigned*)&Bp[n0 + 2 * r + 8]};
            mma_f16(acc[0][nt], af[0], bf);
            mma_f16(acc[1][nt], af[1], bf);
        }
    }

    // epilogue
#pragma unroll
    for (int mt = 0; mt < 2; mt++) {
#pragma unroll
        for (int i2 = 0; i2 < 2; i2++) {
            int row = wm + mt * 16 + (lane >> 2) + 8 * i2;
            int t = t0 + row;
            int w = t >> 6, n = t & 63;
#pragma unroll
            for (int nt = 0; nt < 8; nt++) {
                int col0 = j0 + wn + nt * 8 + (lane & 3) * 2;
                float v0 = acc[mt][nt][i2 * 2 + 0];
                float v1 = acc[mt][nt][i2 * 2 + 1];
                if (MODE == 0) {
#pragma unroll
                    for (int j = 0; j < 2; j++) {
                        int col = col0 + j;
                        float v = (j == 0) ? v0 : v1;
                        int part = col >> 8;
                        int hh = (col >> 5) & 7;
                        int hd = col & 31;
                        if (part == 0) v += bias0[col];
                        else if (part == 2) v += bias1[col - 512];
                        size_t dst = ((size_t)(w * 8 + hh) * 64 + n) * 32 + hd;
                        if (part == 0) g_q[dst] = v;
                        else if (part == 1) g_k[dst] = v;
                        else g_v[dst] = v;
                    }
                } else {
                    v0 += bias0[col0];
                    v1 += bias0[col0 + 1];
                    v0 = 0.5f * v0 * (1.0f + erff(v0 * 0.70710678118654752f));
                    v1 = 0.5f * v1 * (1.0f + erff(v1 * 0.70710678118654752f));
                    __half2 hv = __floats2half2_rn(v0, v1);
                    *(unsigned*)&g_hh[(size_t)t * 1024 + col0] = *(unsigned*)&hv;
                }
            }
        }
    }
}

// ---------------- fp16 GEMM B (fused LN): BM64 BN256 BK16, 4 stages --------
// MODE 1: A=g_attnout, W=proj^T -> +proj_b, LN, +x -> g_x1 (f32) & g_x1h (f16)
// MODE 3: A=g_hh,      W=fc2^T  -> +fc2_b, LN, +g_x1 -> out
template <int MODE>
__global__ void __launch_bounds__(256, 2)
mma_gemm_fused(const float* __restrict__ bias0, const float* __restrict__ gamma,
               const float* __restrict__ beta, const float* __restrict__ basep,
               float* __restrict__ outp, int K) {
    extern __shared__ __align__(16) char dsm[];
    __half* sA = (__half*)dsm;                   // 4 x 1536 halfs
    __half* sB = (__half*)(dsm + F_SB_BASE);     // 4 x 6144 halfs

    const __half* A = (MODE == 1) ? g_attnout : g_hh;
    const __half* W = (MODE == 1) ? (g_whT + 196608) : (g_whT + 524288);

    int tid = threadIdx.x;
    int lane = tid & 31, wid = tid >> 5;
    int wm = (wid & 1) * 32, wn = (wid >> 1) * 64;
    int t0 = blockIdx.x * 64;

    // A producer (tid<128): row = tid>>1, chunk = tid&1
    int rowA = tid >> 1, chA = tid & 1;
    const __half* aSrc = A + (size_t)(t0 + rowA) * (size_t)K + chA * 8;
    uint32_t aDst = smem_u32(sA) + (uint32_t)(rowA * 48 + chA * 16);
    bool doA = (tid < 128);
    // B producers: rows tid>>1 and 128+(tid>>1), chunk tid&1
    const __half* bSrc0 = W + (size_t)(tid >> 1) * K + (tid & 1) * 8;
    const __half* bSrc1 = W + (size_t)(128 + (tid >> 1)) * K + (tid & 1) * 8;
    uint32_t bDst0 = smem_u32(sB) + (uint32_t)((tid >> 1) * 48 + (tid & 1) * 16);
    uint32_t bDst1 = bDst0 + 128 * 48;

    float acc[2][8][4];
#pragma unroll
    for (int mt = 0; mt < 2; mt++)
#pragma unroll
        for (int nt = 0; nt < 8; nt++)
#pragma unroll
            for (int i = 0; i < 4; i++) acc[mt][nt][i] = 0.0f;

    int T = K >> 4;
#pragma unroll
    for (int s = 0; s < 3; s++) {
        if (doA) cp16(aDst + (uint32_t)s * F_STA_B, aSrc + s * 16);
        cp16(bDst0 + (uint32_t)s * F_STB_B, bSrc0 + s * 16);
        cp16(bDst1 + (uint32_t)s * F_STB_B, bSrc1 + s * 16);
        CP_COMMIT();
    }

    int r = lane & 3, q = lane >> 2;
    for (int kt = 0; kt < T; kt++) {
        CP_WAIT2();
        __syncthreads();
        int kn = kt + 3;
        if (kn < T) {
            int st = kn & 3;
            if (doA) cp16(aDst + (uint32_t)st * F_STA_B, aSrc + kn * 16);
            cp16(bDst0 + (uint32_t)st * F_STB_B, bSrc0 + kn * 16);
            cp16(bDst1 + (uint32_t)st * F_STB_B, bSrc1 + kn * 16);
        }
        CP_COMMIT();

        const __half* Ap = sA + (kt & 3) * 1536;
        const __half* Bp = sB + (kt & 3) * 6144;
        unsigned af[2][4];
#pragma unroll
        for (int mt = 0; mt < 2; mt++) {
            int m0 = (wm + mt * 16 + q) * 24;
            af[mt][0] = *(const unsigned*)&Ap[m0 + 2 * r];
            af[mt][1] = *(const unsigned*)&Ap[m0 + 192 + 2 * r];
            af[mt][2] = *(const unsigned*)&Ap[m0 + 2 * r + 8];
            af[mt][3] = *(const unsigned*)&Ap[m0 + 192 + 2 * r + 8];
        }
#pragma unroll
        for (int nt = 0; nt < 8; nt++) {
            int n0 = (wn + nt * 8 + q) * 24;
            unsigned bf[2] = {*(const unsigned*)&Bp[n0 + 2 * r],
                              *(const unsigned*)&Bp[n0 + 2 * r + 8]};
            mma_f16(acc[0][nt], af[0], bf);
            mma_f16(acc[1][nt], af[1], bf);
        }
    }

    // ---- fused epilogue: stage C, per-row LN + residual ----
    __syncthreads();
    float* Cs = (float*)dsm;  // [64][264]
#pragma unroll
    for (int mt = 0; mt < 2; mt++) {
#pragma unroll
        for (int i2 = 0; i2 < 2; i2++) {
            int row = wm + mt * 16 + (lane >> 2) + 8 * i2;
#pragma unroll
            for (int nt = 0; nt < 8; nt++) {
#pragma unroll
                for (int j = 0; j < 2; j++) {
                    int col = wn + nt * 8 + (lane & 3) * 2 + j;
                    Cs[row * 264 + col] = acc[mt][nt][i2 * 2 + j];
                }
            }
        }
    }
    __syncthreads();

    int c8 = lane * 8;
    float4 bv0 = *(const float4*)&bias0[c8];
    float4 bv1 = *(const float4*)&bias0[c8 + 4];
    float4 gv0 = *(const float4*)&gamma[c8];
    float4 gv1 = *(const float4*)&gamma[c8 + 4];
    float4 be0 = *(const float4*)&beta[c8];
    float4 be1 = *(const float4*)&beta[c8 + 4];

    for (int rr = 0; rr < 8; rr++) {
        int row = wid * 8 + rr;
        float4 a = *(const float4*)&Cs[row * 264 + c8];
        float4 c = *(const float4*)&Cs[row * 264 + c8 + 4];
        a.x += bv0.x; a.y += bv0.y; a.z += bv0.z; a.w += bv0.w;
        c.x += bv1.x; c.y += bv1.y; c.z += bv1.z; c.w += bv1.w;
        float s = a.x + a.y + a.z + a.w + c.x + c.y + c.z + c.w;
        float s2 = a.x * a.x + a.y * a.y + a.z * a.z + a.w * a.w +
                   c.x * c.x + c.y * c.y + c.z * c.z + c.w * c.w;
#pragma unroll
        for (int o = 16; o > 0; o >>= 1) {
            s += __shfl_xor_sync(0xffffffffu, s, o);
            s2 += __shfl_xor_sync(0xffffffffu, s2, o);
        }
        float mu = s * (1.0f / 256.0f);
        float var = s2 * (1.0f / 256.0f) - mu * mu;
        float inv = rsqrtf(var + 1e-5f);

        int t = t0 + row;
        size_t p = (MODE == 1) ? nat_pos(t) : (size_t)t;
        size_t off = p * 256 + c8;
        const float* base = (MODE == 1) ? basep : g_x1;
        float4 ba = *(const float4*)&base[off];
        float4 bc = *(const float4*)&base[off + 4];
        float4 r0, r1;
        r0.x = ba.x + (a.x - mu) * inv * gv0.x + be0.x;
        r0.y = ba.y + (a.y - mu) * inv * gv0.y + be0.y;
        r0.z = ba.z + (a.z - mu) * inv * gv0.z + be0.z;
        r0.w = ba.w + (a.w - mu) * inv * gv0.w + be0.w;
        r1.x = bc.x + (c.x - mu) * inv * gv1.x + be1.x;
        r1.y = bc.y + (c.y - mu) * inv * gv1.y + be1.y;
        r1.z = bc.z + (c.z - mu) * inv * gv1.z + be1.z;
        r1.w = bc.w + (c.w - mu) * inv * gv1.w + be1.w;
        if (MODE == 1) {
            *(float4*)&g_x1[off] = r0;
            *(float4*)&g_x1[off + 4] = r1;
            __half2 h0 = __floats2half2_rn(r0.x, r0.y);
            __half2 h1 = __floats2half2_rn(r0.z, r0.w);
            __half2 h2 = __floats2half2_rn(r1.x, r1.y);
            __half2 h3 = __floats2half2_rn(r1.z, r1.w);
            *(uint2*)&g_x1h[off] = make_uint2(*(unsigned*)&h0, *(unsigned*)&h1);
            *(uint2*)&g_x1h[off + 4] = make_uint2(*(unsigned*)&h2, *(unsigned*)&h3);
        } else {
            *(float4*)&outp[off] = r0;
            *(float4*)&outp[off + 4] = r1;
        }
    }
}

// ---------------- windowed cosine attention ----------------
__global__ void attn_kernel(const float* __restrict__ logit_scale) {
    __shared__ __align__(16) float qT[32][68];
    __shared__ __align__(16) float kT[32][68];
    __shared__ __align__(16) float vS[64][32];
    __shared__ __align__(16) float S[64][68];
    __shared__ float qn[64], kn[64];

    int w = blockIdx.x, h = blockIdx.y;
    int tid = threadIdx.x;
    size_t base = (size_t)(w * 8 + h) * 2048;

    for (int idx = tid; idx < 2048; idx += 256) {
        int n = idx >> 5, d = idx & 31;
        qT[d][n] = g_q[base + idx];
        kT[d][n] = g_k[base + idx];
        vS[n][d] = g_v[base + idx];
    }
    __syncthreads();

    float sc = __expf(fminf(logit_scale[h], LOGIT_MAX));
    if (tid < 64) {
        float s = 0.0f;
#pragma unroll
        for (int d = 0; d < 32; d++) s = fmaf(qT[d][tid], qT[d][tid], s);
        qn[tid] = rsqrtf(fmaxf(s, 1e-12f)) * sc;
    } else if (tid < 128) {
        int n = tid - 64;
        float s = 0.0f;
#pragma unroll
        for (int d = 0; d < 32; d++) s = fmaf(kT[d][n], kT[d][n], s);
        kn[n] = rsqrtf(fmaxf(s, 1e-12f));
    }
    __syncthreads();

    for (int idx = tid; idx < 2048; idx += 256) {
        int d = idx >> 6, n = idx & 63;
        qT[d][n] *= qn[n];
        kT[d][n] *= kn[n];
    }
    __syncthreads();

    int ty = tid >> 4, tx = tid & 15;
    float acc[4][4];
#pragma unroll
    for (int i = 0; i < 4; i++)
#pragma unroll
        for (int j = 0; j < 4; j++) acc[i][j] = 0.0f;

#pragma unroll
    for (int kk = 0; kk < 32; kk++) {
        float4 avv = *(const float4*)&qT[kk][ty * 4];
        float4 bvv = *(const float4*)&kT[kk][tx * 4];
        float a4[4] = {avv.x, avv.y, avv.z, avv.w};
        float b4[4] = {bvv.x, bvv.y, bvv.z, bvv.w};
#pragma unroll
        for (int i = 0; i < 4; i++)
#pragma unroll
            for (int j = 0; j < 4; j++) acc[i][j] = fmaf(a4[i], b4[j], acc[i][j]);
    }

    int wi = w & 63;
    int cls = (((wi >> 3) == 7) ? 1 : 0) | (((wi & 7) == 7) ? 2 : 0);
    const float* Bp = g_bias + ((size_t)(cls * 8 + h) << 12);
#pragma unroll
    for (int i = 0; i < 4; i++) {
        int ri = ty * 4 + i;
        float4 bv = *(const float4*)&Bp[ri * 64 + tx * 4];
        float v4[4];
        v4[0] = acc[i][0] + bv.x;
        v4[1] = acc[i][1] + bv.y;
        v4[2] = acc[i][2] + bv.z;
        v4[3] = acc[i][3] + bv.w;
        float m = fmaxf(fmaxf(v4[0], v4[1]), fmaxf(v4[2], v4[3]));
#pragma unroll
        for (int o = 8; o > 0; o >>= 1) m = fmaxf(m, __shfl_xor_sync(0xffffffffu, m, o));
        float s = 0.0f;
#pragma unroll
        for (int j = 0; j < 4; j++) {
            v4[j] = __expf(v4[j] - m);
            s += v4[j];
        }
#pragma unroll
        for (int o = 8; o > 0; o >>= 1) s += __shfl_xor_sync(0xffffffffu, s, o);
        float inv = 1.0f / s;
        float4 sv = make_float4(v4[0] * inv, v4[1] * inv, v4[2] * inv, v4[3] * inv);
        *(float4*)&S[ri][tx * 4] = sv;
    }
    __syncthreads();

    int ty2 = tid >> 3, tx2 = tid & 7;
    float o0[4] = {0, 0, 0, 0}, o1[4] = {0, 0, 0, 0};
#pragma unroll
    for (int mb = 0; mb < 16; mb++) {
        float4 s0 = *(const float4*)&S[ty2][mb * 4];
        float4 s1 = *(const float4*)&S[ty2 + 32][mb * 4];
        float p0[4] = {s0.x, s0.y, s0.z, s0.w};
        float p1[4] = {s1.x, s1.y, s1.z, s1.w};
#pragma unroll
        for (int e = 0; e < 4; e++) {
            float4 vv = *(const float4*)&vS[mb * 4 + e][tx2 * 4];
            float v4[4] = {vv.x, vv.y, vv.z, vv.w};
#pragma unroll
            for (int j = 0; j < 4; j++) {
                o0[j] = fmaf(p0[e], v4[j], o0[j]);
                o1[j] = fmaf(p1[e], v4[j], o1[j]);
            }
        }
    }
    {
        size_t d0 = (size_t)(w * 64 + ty2) * 256 + h * 32 + tx2 * 4;
        size_t d1 = (size_t)(w * 64 + ty2 + 32) * 256 + h * 32 + tx2 * 4;
        __half2 a0 = __floats2half2_rn(o0[0], o0[1]);
        __half2 a1 = __floats2half2_rn(o0[2], o0[3]);
        __half2 b0 = __floats2half2_rn(o1[0], o1[1]);
        __half2 b1 = __floats2half2_rn(o1[2], o1[3]);
        *(uint2*)&g_attnout[d0] = make_uint2(*(unsigned*)&a0, *(unsigned*)&a1);
        *(uint2*)&g_attnout[d1] = make_uint2(*(unsigned*)&b0, *(unsigned*)&b1);
    }
}

// ---------------- launch ----------------
extern "C" void kernel_launch(void* const* d_in, const int* in_sizes, int n_in,
                              void* d_out, int out_size) {
    const float* x = (const float*)d_in[0];
    const float* qkv_w = (const float*)d_in[1];
    const float* q_bias = (const float*)d_in[2];
    const float* v_bias = (const float*)d_in[3];
    const float* logit_scale = (const float*)d_in[4];
    const float* cpb_w1 = (const float*)d_in[5];
    const float* cpb_b1 = (const float*)d_in[6];
    const float* cpb_w2 = (const float*)d_in[7];
    const float* proj_b = (const float*)d_in[9];
    const float* norm1_g = (const float*)d_in[10];
    const float* norm1_b = (const float*)d_in[11];
    const float* fc1_b = (const float*)d_in[13];
    const float* fc2_b = (const float*)d_in[15];
    const float* norm2_g = (const float*)d_in[16];
    const float* norm2_b = (const float*)d_in[17];
    const float* proj_w = (const float*)d_in[8];
    const float* fc1_w = (const float*)d_in[12];
    const float* fc2_w = (const float*)d_in[14];
    float* out = (float*)d_out;

    static int smem_set = 0;
    if (!smem_set) {
        cudaFuncSetAttribute(mma_gemm<0>, cudaFuncAttributeMaxDynamicSharedMemorySize, G_DSM);
        cudaFuncSetAttribute(mma_gemm<2>, cudaFuncAttributeMaxDynamicSharedMemorySize, G_DSM);
        cudaFuncSetAttribute(mma_gemm_fused<1>, cudaFuncAttributeMaxDynamicSharedMemorySize, F_DSM);
        cudaFuncSetAttribute(mma_gemm_fused<3>, cudaFuncAttributeMaxDynamicSharedMemorySize, F_DSM);
        smem_set = 1;
    }

    half_w_kernel<<<512, 256>>>(qkv_w, proj_w, fc1_w, fc2_w);
    x_half_kernel<<<512, 256>>>(x);
    cpb_kernel<<<225, 256>>>(cpb_w1, cpb_b1, cpb_w2);
    bias_kernel<<<32, 256>>>();

    mma_gemm<0><<<dim3(6, 1024), 256, G_DSM>>>(q_bias, v_bias, 768, 256);
    attn_kernel<<<dim3(2048, 8), 256>>>(logit_scale);
    mma_gemm_fused<1><<<2048, 256, F_DSM>>>(proj_b, norm1_g, norm1_b, x, nullptr, 256);
    mma_gemm<2><<<dim3(8, 1024), 256, G_DSM>>>(fc1_b, nullptr, 1024, 256);
    mma_gemm_fused<3><<<2048, 256, F_DSM>>>(fc2_b, norm2_g, norm2_b, nullptr, out, 1024);

    (void)in_sizes; (void)n_in; (void)out_size;
}